// round 14
// baseline (speedup 1.0000x reference)
#include <cuda_runtime.h>
#include <math.h>

#define BB   128
#define NKG  500
#define NN   502
#define DD   1024
#define HH   256
#define EE   4000
#define NBTOT (BB*NN)
#define ZROWS (NN + BB*NN)
#define MSUB  (EE + NN)

typedef unsigned long long ull;

struct __align__(16) Scratch {
    float hb[640*HH];
    float a1[NN*HH], a2[NN*HH], a3[NN*HH];
    float zd1[(size_t)ZROWS*HH];
    float g2 [(size_t)ZROWS*HH];
    float zd2[(size_t)ZROWS*HH];
    float g3 [(size_t)ZROWS*HH];
    float dy2[(size_t)BB*NN*HH];
    float dy3[(size_t)BB*NN*HH];
    float csr_norm[EE];
    float sub2_nrm[MSUB], sub3_nrm[MSUB];
    float c[NN], dinv[NN];
    float accA[3][HH], accAsq[3][HH], accD[3][HH], accDsq[3][HH], accAD[3][HH];
    float accS[HH], accS2[HH], accAc[HH];
    float sc[3][HH], sh[3][HH];
    int   csr_src[EE];
    int   sub2_src[MSUB], sub3_src[MSUB];
    int   off[NN+1], soff2[NN+1], soff3[NN+1];
    int   slot1[NN], slot2[NN], slot3[NN];
    int   list1[NN], list2[NN], list3[NN];
    int   m1, m2, m3;
    int   ctr[4];
    int   flg[4];
};
__device__ Scratch S;

__device__ __forceinline__ float elu_f(float x) { return x > 0.f ? x : expm1f(x); }
__device__ __forceinline__ int clampn(int v) { return v < 0 ? 0 : (v >= NN ? NN - 1 : v); }
__device__ __forceinline__ void fma2(ull& d, ull a, ull b) {
    asm("fma.rn.f32x2 %0, %1, %2, %0;" : "+l"(d) : "l"(a), "l"(b));
}
__device__ __forceinline__ ull pk2(float x) {
    ull r; asm("mov.b64 %0, {%1, %1};" : "=l"(r) : "f"(x)); return r;
}
// block-wide wait on device flag; finalizer sets it after threadfence
__device__ __forceinline__ void wait_flag(int* f) {
    if (threadIdx.x == 0) {
        while (atomicAdd(f, 0) == 0) __nanosleep(64);
    }
    __syncthreads();
    __threadfence();
}

// ---------------------------------------------------------------------------
// merged init + graph topology. grid 322, block 512.
//   blocks 0..319 : zero hb (2 rows each)
//   block 320     : zero accumulators/counters/flags
//   block 321     : full topology pass (CSR, c, compactions, sub-CSRs)
// ---------------------------------------------------------------------------
__global__ __launch_bounds__(512) void k_initgraph(Scratch* s, const int* __restrict__ ei) {
    __shared__ unsigned short esrc[EE], edst[EE];
    __shared__ int   cnt[NN];
    __shared__ int   sm[512];
    __shared__ float dsh[NN];
    __shared__ float cc[NN];
    __shared__ int   sl1[NN];
    __shared__ int   sl2[NN];
    __shared__ int   mk[NN];
    __shared__ int   lst[NN];
    __shared__ int   mcur;
    int bb = blockIdx.x, t = threadIdx.x;

    if (bb < 320) {
        s->hb[(size_t)(bb*2)*HH + (t & 255) + ((t >> 8) ? HH : 0)] = 0.f;
        // each block zeroes rows 2bb and 2bb+1: t in [0,256) -> row 2bb, t in [256,512) -> row 2bb+1
        return;
    }
    if (bb == 320) {
        if (t < HH) {
            for (int l = 0; l < 3; l++) {
                s->accA[l][t]=0.f; s->accAsq[l][t]=0.f;
                s->accD[l][t]=0.f; s->accDsq[l][t]=0.f; s->accAD[l][t]=0.f;
            }
            s->accS[t]=0.f; s->accS2[t]=0.f; s->accAc[t]=0.f;
        }
        if (t < 4) { s->ctr[t] = 0; s->flg[t] = 0; }
        return;
    }

    // ---- block 321: topology ----
    for (int e = t; e < EE; e += 512) {
        esrc[e] = (unsigned short)clampn(ei[e]);
        edst[e] = (unsigned short)clampn(ei[EE + e]);
    }
    if (t < NN) cnt[t] = 0;
    __syncthreads();
    for (int e = t; e < EE; e += 512) atomicAdd(&cnt[edst[e]], 1);
    __syncthreads();

    int deg = (t < NN) ? cnt[t] : 0;
    float di = rsqrtf((float)(deg + 1));
    if (t < NN) { s->dinv[t] = di; dsh[t] = di; }

    sm[t] = deg; __syncthreads();
    for (int d = 1; d < 512; d <<= 1) {
        int x = (t >= d) ? sm[t - d] : 0; __syncthreads();
        sm[t] += x; __syncthreads();
    }
    if (t < NN) s->off[t] = sm[t] - deg;
    if (t == 0) s->off[NN] = sm[NN - 1];
    if (t < NN) cnt[t] = 0;
    __syncthreads();

    for (int e = t; e < EE; e += 512) {
        int src = esrc[e], dst = edst[e];
        int p = s->off[dst] + atomicAdd(&cnt[dst], 1);
        s->csr_src[p] = src;
        s->csr_norm[p] = dsh[src] * dsh[dst];
    }

    if (t < NN) cc[t] = 0.f;
    __syncthreads();
    for (int e = t; e < EE; e += 512) {
        if (esrc[e] == NKG) {
            int dst = edst[e];
            atomicAdd(&cc[dst], dsh[NKG] * dsh[dst]);
        }
    }
    __syncthreads();
    if (t == NKG) cc[t] += dsh[NKG] * dsh[NKG];
    __syncthreads();
    if (t < NN) s->c[t] = cc[t];

    // compact 1
    int f = (t < NN) && (cc[t] > 0.f);
    sm[t] = f; __syncthreads();
    for (int d = 1; d < 512; d <<= 1) {
        int x = (t >= d) ? sm[t - d] : 0; __syncthreads();
        sm[t] += x; __syncthreads();
    }
    if (t < NN) {
        int sl = f ? sm[t] - 1 : -1;
        sl1[t] = sl; s->slot1[t] = sl;
        if (f) s->list1[sm[t] - 1] = t;
    }
    if (t == 0) s->m1 = sm[NN - 1];
    __syncthreads();

    // mark2 + compact 2
    if (t < NN) mk[t] = (sl1[t] >= 0) ? 1 : 0;
    __syncthreads();
    for (int e = t; e < EE; e += 512)
        if (sl1[esrc[e]] >= 0) mk[edst[e]] = 1;
    __syncthreads();
    f = (t < NN) && mk[t];
    sm[t] = f; __syncthreads();
    for (int d = 1; d < 512; d <<= 1) {
        int x = (t >= d) ? sm[t - d] : 0; __syncthreads();
        sm[t] += x; __syncthreads();
    }
    if (t < NN) {
        int sl = f ? sm[t] - 1 : -1;
        sl2[t] = sl; s->slot2[t] = sl;
        if (f) { s->list2[sm[t] - 1] = t; lst[sm[t] - 1] = t; }
    }
    if (t == 0) { s->m2 = sm[NN - 1]; mcur = sm[NN - 1]; }
    __syncthreads();

    // sub-CSR layer 2
    {
        int degj = 0;
        if (t < mcur) {
            int n = lst[t];
            if (sl1[n] >= 0) degj++;
            int e1 = s->off[n + 1];
            for (int e = s->off[n]; e < e1; e++)
                if (sl1[s->csr_src[e]] >= 0) degj++;
        }
        sm[t] = degj; __syncthreads();
        for (int d = 1; d < 512; d <<= 1) {
            int x = (t >= d) ? sm[t - d] : 0; __syncthreads();
            sm[t] += x; __syncthreads();
        }
        if (t < mcur) {
            int o = sm[t] - degj;
            s->soff2[t] = o;
            int n = lst[t];
            if (sl1[n] >= 0) { s->sub2_src[o] = sl1[n]; s->sub2_nrm[o] = dsh[n]*dsh[n]; o++; }
            int e1 = s->off[n + 1];
            for (int e = s->off[n]; e < e1; e++) {
                int sp = sl1[s->csr_src[e]];
                if (sp >= 0) { s->sub2_src[o] = sp; s->sub2_nrm[o] = s->csr_norm[e]; o++; }
            }
        }
        if (t == 0) s->soff2[mcur] = sm[511];
        __syncthreads();
    }

    // mark3 + compact 3
    if (t < NN) mk[t] = (sl2[t] >= 0) ? 1 : 0;
    __syncthreads();
    for (int e = t; e < EE; e += 512)
        if (sl2[esrc[e]] >= 0) mk[edst[e]] = 1;
    __syncthreads();
    f = (t < NN) && mk[t];
    sm[t] = f; __syncthreads();
    for (int d = 1; d < 512; d <<= 1) {
        int x = (t >= d) ? sm[t - d] : 0; __syncthreads();
        sm[t] += x; __syncthreads();
    }
    if (t < NN) {
        s->slot3[t] = f ? sm[t] - 1 : -1;
        if (f) { s->list3[sm[t] - 1] = t; lst[sm[t] - 1] = t; }
    }
    if (t == 0) { s->m3 = sm[NN - 1]; mcur = sm[NN - 1]; }
    __syncthreads();

    // sub-CSR layer 3
    {
        int degj = 0;
        if (t < mcur) {
            int n = lst[t];
            if (sl2[n] >= 0) degj++;
            int e1 = s->off[n + 1];
            for (int e = s->off[n]; e < e1; e++)
                if (sl2[s->csr_src[e]] >= 0) degj++;
        }
        sm[t] = degj; __syncthreads();
        for (int d = 1; d < 512; d <<= 1) {
            int x = (t >= d) ? sm[t - d] : 0; __syncthreads();
            sm[t] += x; __syncthreads();
        }
        if (t < mcur) {
            int o = sm[t] - degj;
            s->soff3[t] = o;
            int n = lst[t];
            if (sl2[n] >= 0) { s->sub3_src[o] = sl2[n]; s->sub3_nrm[o] = dsh[n]*dsh[n]; o++; }
            int e1 = s->off[n + 1];
            for (int e = s->off[n]; e < e1; e++) {
                int sp = sl2[s->csr_src[e]];
                if (sp >= 0) { s->sub3_src[o] = sp; s->sub3_nrm[o] = s->csr_norm[e]; o++; }
            }
        }
        if (t == 0) s->soff3[mcur] = sm[511];
    }
}

// ---------------------------------------------------------------------------
// layer-1 GEMM: 64x128 tile, split-K 8, f32x2, atomic accumulate
// ---------------------------------------------------------------------------
__global__ void k_gemm1(const float* __restrict__ basev, const float* __restrict__ sensor,
                        const float* __restrict__ W, float* __restrict__ hb) {
    int rb = blockIdx.x * 64, cb = blockIdx.y * 128, kc = blockIdx.z * 128;
    __shared__ __align__(16) float As[16][64];
    __shared__ __align__(16) float Ws[16][128];
    int tid = threadIdx.x;
    int tm = (tid >> 4) << 2, tn = (tid & 15) << 3;
    ull acc[4][4];
#pragma unroll
    for (int i = 0; i < 4; i++)
#pragma unroll
        for (int j = 0; j < 4; j++) acc[i][j] = 0ull;
    int r = tid >> 2, kk = (tid & 3) << 2;
    for (int k0 = kc; k0 < kc + 128; k0 += 16) {
        {
            int row = rb + r;
            float4 av = make_float4(0.f, 0.f, 0.f, 0.f);
            if (row < NKG)           av = *(const float4*)(basev  + (size_t)row * DD + k0 + kk);
            else if (row < NKG + BB) av = *(const float4*)(sensor + (size_t)(row - NKG) * DD + k0 + kk);
            As[kk][r]=av.x; As[kk+1][r]=av.y; As[kk+2][r]=av.z; As[kk+3][r]=av.w;
        }
#pragma unroll
        for (int ld = 0; ld < 2; ld++) {
            int idx = tid + ld * 256;
            int wr = idx >> 5, wc = (idx & 31) << 2;
            *(float4*)&Ws[wr][wc] = *(const float4*)(W + (size_t)(k0 + wr) * HH + cb + wc);
        }
        __syncthreads();
#pragma unroll
        for (int q = 0; q < 16; q++) {
            float4 a = *(const float4*)&As[q][tm];
            ull b0 = *(const ull*)&Ws[q][tn];
            ull b1 = *(const ull*)&Ws[q][tn+2];
            ull b2 = *(const ull*)&Ws[q][tn+4];
            ull b3 = *(const ull*)&Ws[q][tn+6];
            ull ap0 = pk2(a.x), ap1 = pk2(a.y), ap2 = pk2(a.z), ap3 = pk2(a.w);
            fma2(acc[0][0],ap0,b0); fma2(acc[0][1],ap0,b1); fma2(acc[0][2],ap0,b2); fma2(acc[0][3],ap0,b3);
            fma2(acc[1][0],ap1,b0); fma2(acc[1][1],ap1,b1); fma2(acc[1][2],ap1,b2); fma2(acc[1][3],ap1,b3);
            fma2(acc[2][0],ap2,b0); fma2(acc[2][1],ap2,b1); fma2(acc[2][2],ap2,b2); fma2(acc[2][3],ap2,b3);
            fma2(acc[3][0],ap3,b0); fma2(acc[3][1],ap3,b1); fma2(acc[3][2],ap3,b2); fma2(acc[3][3],ap3,b3);
        }
        __syncthreads();
    }
#pragma unroll
    for (int i = 0; i < 4; i++) {
        int row = rb + tm + i;
        if (row < NKG + BB) {
            float* p = hb + (size_t)row * HH + cb + tn;
#pragma unroll
            for (int j = 0; j < 4; j++) {
                float2 v = *reinterpret_cast<float2*>(&acc[i][j]);
                atomicAdd(p + 2*j, v.x); atomicAdd(p + 2*j + 1, v.y);
            }
        }
    }
}

// ---------------------------------------------------------------------------
// generic GEMM: C[M,256] = A[M,256] @ W[256,256], 64x128, f32x2
// ---------------------------------------------------------------------------
__global__ void k_gemm(const float* __restrict__ A, const float* __restrict__ W,
                       float* __restrict__ C, int Mbase,
                       const int* __restrict__ mptr, int mmul) {
    int M = Mbase + (mptr ? (*mptr) * mmul : 0);
    int rb = blockIdx.x * 64;
    if (rb >= M) return;
    int cb = blockIdx.y * 128;
    __shared__ __align__(16) float As[16][64];
    __shared__ __align__(16) float Ws[16][128];
    int tid = threadIdx.x;
    int tm = (tid >> 4) << 2, tn = (tid & 15) << 3;
    ull acc[4][4];
#pragma unroll
    for (int i = 0; i < 4; i++)
#pragma unroll
        for (int j = 0; j < 4; j++) acc[i][j] = 0ull;
    int r = tid >> 2, kk = (tid & 3) << 2;
    for (int k0 = 0; k0 < HH; k0 += 16) {
        {
            float4 av = make_float4(0.f, 0.f, 0.f, 0.f);
            if (rb + r < M) av = *(const float4*)(A + (size_t)(rb + r) * HH + k0 + kk);
            As[kk][r]=av.x; As[kk+1][r]=av.y; As[kk+2][r]=av.z; As[kk+3][r]=av.w;
        }
#pragma unroll
        for (int ld = 0; ld < 2; ld++) {
            int idx = tid + ld * 256;
            int wr = idx >> 5, wc = (idx & 31) << 2;
            *(float4*)&Ws[wr][wc] = *(const float4*)(W + (size_t)(k0 + wr) * HH + cb + wc);
        }
        __syncthreads();
#pragma unroll
        for (int q = 0; q < 16; q++) {
            float4 a = *(const float4*)&As[q][tm];
            ull b0 = *(const ull*)&Ws[q][tn];
            ull b1 = *(const ull*)&Ws[q][tn+2];
            ull b2 = *(const ull*)&Ws[q][tn+4];
            ull b3 = *(const ull*)&Ws[q][tn+6];
            ull ap0 = pk2(a.x), ap1 = pk2(a.y), ap2 = pk2(a.z), ap3 = pk2(a.w);
            fma2(acc[0][0],ap0,b0); fma2(acc[0][1],ap0,b1); fma2(acc[0][2],ap0,b2); fma2(acc[0][3],ap0,b3);
            fma2(acc[1][0],ap1,b0); fma2(acc[1][1],ap1,b1); fma2(acc[1][2],ap1,b2); fma2(acc[1][3],ap1,b3);
            fma2(acc[2][0],ap2,b0); fma2(acc[2][1],ap2,b1); fma2(acc[2][2],ap2,b2); fma2(acc[2][3],ap2,b3);
            fma2(acc[3][0],ap3,b0); fma2(acc[3][1],ap3,b1); fma2(acc[3][2],ap3,b2); fma2(acc[3][3],ap3,b3);
        }
        __syncthreads();
    }
#pragma unroll
    for (int i = 0; i < 4; i++) {
        int row = rb + tm + i;
        if (row < M) {
            ull* p = (ull*)(C + (size_t)row * HH + cb + tn);
            p[0]=acc[i][0]; p[1]=acc[i][1]; p[2]=acc[i][2]; p[3]=acc[i][3];
        }
    }
}

// ---------------------------------------------------------------------------
// layer-1: PURE base aggregation — grid NN
// ---------------------------------------------------------------------------
__global__ __launch_bounds__(256, 8) void k_agg1(Scratch* s, const float* __restrict__ b1) {
    int n = blockIdx.x, h = threadIdx.x;
    float acc = b1[h];
    int e0 = s->off[n], e1 = s->off[n + 1];
    int e = e0;
    for (; e + 3 < e1; e += 4) {
        int s0 = s->csr_src[e],   s1x = s->csr_src[e+1];
        int s2 = s->csr_src[e+2], s3x = s->csr_src[e+3];
        float n0 = s->csr_norm[e],   n1 = s->csr_norm[e+1];
        float n2 = s->csr_norm[e+2], n3 = s->csr_norm[e+3];
        float v0 = (s0  < NKG) ? s->hb[(size_t)s0  * HH + h] : 0.f;
        float v1 = (s1x < NKG) ? s->hb[(size_t)s1x * HH + h] : 0.f;
        float v2 = (s2  < NKG) ? s->hb[(size_t)s2  * HH + h] : 0.f;
        float v3 = (s3x < NKG) ? s->hb[(size_t)s3x * HH + h] : 0.f;
        acc += n0*v0 + n1*v1 + n2*v2 + n3*v3;
    }
    for (; e < e1; e++) {
        int src = s->csr_src[e];
        if (src < NKG) acc += s->csr_norm[e] * s->hb[(size_t)src * HH + h];
    }
    float di = s->dinv[n];
    if (n < NKG) acc += di * di * s->hb[(size_t)n * HH + h];
    s->a1[n * HH + h] = acc;
}

// ---------------------------------------------------------------------------
// layer-1 fused stats+finalize+materialize: grid 16 + NN + BB
//   blocks 0..15: stats + ticketed finalize -> sc/sh[0], then flg[0]=1
//   blocks 16.. : wait flg[0], then zd1 body
// ---------------------------------------------------------------------------
__global__ __launch_bounds__(256, 8) void k_zd1f(Scratch* s, const float* __restrict__ gamma,
                                                 const float* __restrict__ beta) {
    int bb = blockIdx.x, h = threadIdx.x;
    if (bb < 16) {
        if (bb < 12) {
            float sA = 0.f, sA2 = 0.f, sAc = 0.f;
            for (int n = bb; n < NN; n += 12) {
                float A = s->a1[n * HH + h], cv = s->c[n];
                sA += A; sA2 += A * A; sAc += A * cv;
            }
            atomicAdd(&s->accA[0][h], sA);
            atomicAdd(&s->accAsq[0][h], sA2);
            atomicAdd(&s->accAc[h], sAc);
        } else {
            int k = bb - 12;
            float ss = 0.f, ss2 = 0.f;
            for (int b = k; b < BB; b += 4) {
                float v = s->hb[(size_t)(NKG + b) * HH + h];
                ss += v; ss2 += v * v;
            }
            atomicAdd(&s->accS[h], ss);
            atomicAdd(&s->accS2[h], ss2);
        }
        __threadfence();
        __syncthreads();
        __shared__ int ticket;
        if (h == 0) ticket = atomicAdd(&s->ctr[0], 1);
        __syncthreads();
        if (ticket == 15) {
            __threadfence();
            __shared__ float r1[256], r2[256];
            float lc = 0.f, lc2 = 0.f;
            for (int n = h; n < NN; n += 256) { float cv = s->c[n]; lc += cv; lc2 += cv * cv; }
            r1[h] = lc; r2[h] = lc2; __syncthreads();
            for (int d = 128; d > 0; d >>= 1) {
                if (h < d) { r1[h] += r1[h + d]; r2[h] += r2[h + d]; }
                __syncthreads();
            }
            float Ec  = r1[0] / NN, Ec2 = r2[0] / NN;
            float EA  = s->accA[0][h] / NN, EA2 = s->accAsq[0][h] / NN, EAc = s->accAc[h] / NN;
            float Es  = s->accS[h] / BB,  Es2 = s->accS2[h] / BB;
            float mu  = EA + Ec * Es;
            float ey2 = EA2 + 2.f * EAc * Es + Ec2 * Es2;
            float rstd = rsqrtf(ey2 - mu * mu + 1e-5f);
            float scv = rstd * gamma[h];
            s->sc[0][h] = scv; s->sh[0][h] = beta[h] - mu * scv;
            __syncthreads();
            if (h == 0) { __threadfence(); atomicExch(&s->flg[0], 1); }
        }
        return;
    }
    wait_flag(&s->flg[0]);
    int idx = bb - 16;
    float scv = s->sc[0][h], shv = s->sh[0][h];
    if (idx < NN) {
        float v = (s->slot1[idx] >= 0) ? 0.f : elu_f(s->a1[idx * HH + h] * scv + shv);
        s->zd1[(size_t)idx * HH + h] = v;
    } else {
        int b = idx - NN, m = s->m1;
        float sv = s->hb[(size_t)(NKG + b) * HH + h];
        for (int j = 0; j < m; j++) {
            int n = s->list1[j];
            float v = (s->a1[n * HH + h] + s->c[n] * sv) * scv + shv;
            s->zd1[(size_t)(NN + b * m + j) * HH + h] = elu_f(v);
        }
    }
}

// ---------------------------------------------------------------------------
// layers 2/3: COMBINED stats-free base + b-parallel dep aggregation
// ---------------------------------------------------------------------------
__global__ __launch_bounds__(256, 8) void k_aggs(Scratch* s, const float* __restrict__ bias, int layer) {
    int bb = blockIdx.x, h = threadIdx.x;
    const float* g = (layer == 2) ? s->g2 : s->g3;
    if (bb < NN) {
        int n = bb;
        float di = s->dinv[n];
        float acc = bias[h] + di * di * g[(size_t)n * HH + h];
        int e0 = s->off[n], e1 = s->off[n + 1];
        int e = e0;
        for (; e + 3 < e1; e += 4) {
            int s0 = s->csr_src[e],   s1x = s->csr_src[e+1];
            int s2 = s->csr_src[e+2], s3x = s->csr_src[e+3];
            float n0 = s->csr_norm[e],   n1 = s->csr_norm[e+1];
            float n2 = s->csr_norm[e+2], n3 = s->csr_norm[e+3];
            acc += n0 * g[(size_t)s0 * HH + h] + n1 * g[(size_t)s1x * HH + h]
                 + n2 * g[(size_t)s2 * HH + h] + n3 * g[(size_t)s3x * HH + h];
        }
        for (; e < e1; e++)
            acc += s->csr_norm[e] * g[(size_t)s->csr_src[e] * HH + h];
        ((layer == 2) ? s->a2 : s->a3)[n * HH + h] = acc;
    } else {
        int idx = bb - NN, b = idx >> 3, j0 = idx & 7;
        int m  = (layer == 2) ? s->m2 : s->m3;
        int mp = (layer == 2) ? s->m1 : s->m2;
        const int*   soff = (layer == 2) ? s->soff2 : s->soff3;
        const int*   ssrc = (layer == 2) ? s->sub2_src : s->sub3_src;
        const float* snrm = (layer == 2) ? s->sub2_nrm : s->sub3_nrm;
        float* dy = (layer == 2) ? s->dy2 : s->dy3;
        const float* gb = g + (size_t)(NN + b * mp) * HH + h;
        for (int j = j0; j < m; j += 8) {
            int e0 = soff[j], e1 = soff[j + 1];
            float acc = 0.f;
            int e = e0;
            for (; e + 3 < e1; e += 4) {
                int p0 = ssrc[e],   p1 = ssrc[e+1];
                int p2 = ssrc[e+2], p3 = ssrc[e+3];
                float q0 = snrm[e],   q1 = snrm[e+1];
                float q2 = snrm[e+2], q3 = snrm[e+3];
                acc += q0 * gb[(size_t)p0 * HH] + q1 * gb[(size_t)p1 * HH]
                     + q2 * gb[(size_t)p2 * HH] + q3 * gb[(size_t)p3 * HH];
            }
            for (; e < e1; e++)
                acc += snrm[e] * gb[(size_t)ssrc[e] * HH];
            dy[(size_t)(b * m + j) * HH + h] = acc;
        }
    }
}

// ---------------------------------------------------------------------------
// shared device helper: layer-2/3 stats + finalize (called by fused kernels)
// blocks bb in [0,96): 0..15 statsA, 16..95 statsD; ticket; last finalizes
// ---------------------------------------------------------------------------
__device__ void stats_fin(Scratch* s, const float* gamma, const float* beta,
                          int layer, int bb, int h) {
    int L = layer - 1;
    int m = (layer == 2) ? s->m2 : s->m3;
    const float* a = (layer == 2) ? s->a2 : s->a3;
    if (bb < 16) {
        float sA = 0.f, sA2 = 0.f;
        for (int n = bb; n < NN; n += 16) {
            float v = a[n * HH + h]; sA += v; sA2 += v * v;
        }
        atomicAdd(&s->accA[L][h], sA);
        atomicAdd(&s->accAsq[L][h], sA2);
    } else {
        const float* dy = (layer == 2) ? s->dy2 : s->dy3;
        const int* list = (layer == 2) ? s->list2 : s->list3;
        int R = BB * m;
        float sd = 0.f, sd2 = 0.f, sad = 0.f;
        for (int rr = bb - 16; rr < R; rr += 80) {
            int j = rr % m;
            float dv = dy[(size_t)rr * HH + h];
            float A  = a[list[j] * HH + h];
            sd += dv; sd2 += dv * dv; sad += A * dv;
        }
        atomicAdd(&s->accD[L][h], sd);
        atomicAdd(&s->accDsq[L][h], sd2);
        atomicAdd(&s->accAD[L][h], sad);
    }
    __threadfence();
    __syncthreads();
    __shared__ int ticket;
    if (h == 0) ticket = atomicAdd(&s->ctr[L], 1);
    __syncthreads();
    if (ticket == 95) {
        __threadfence();
        float mu  = (BB * s->accA[L][h] + s->accD[L][h]) * (1.f / NBTOT);
        float ey2 = (BB * s->accAsq[L][h] + 2.f * s->accAD[L][h] + s->accDsq[L][h]) * (1.f / NBTOT);
        float rstd = rsqrtf(ey2 - mu * mu + 1e-5f);
        float scv = rstd * gamma[h];
        s->sc[L][h] = scv; s->sh[L][h] = beta[h] - mu * scv;
        __syncthreads();
        if (h == 0) { __threadfence(); atomicExch(&s->flg[L], 1); }
    }
}

// ---------------------------------------------------------------------------
// layer-2 fused stats+finalize+materialize: grid 96 + NN + BB*2
// ---------------------------------------------------------------------------
__global__ __launch_bounds__(256, 8) void k_zd2f(Scratch* s, const float* __restrict__ gamma,
                                                 const float* __restrict__ beta) {
    int bb = blockIdx.x, h = threadIdx.x;
    if (bb < 96) { stats_fin(s, gamma, beta, 2, bb, h); return; }
    wait_flag(&s->flg[1]);
    int idx = bb - 96;
    float scv = s->sc[1][h], shv = s->sh[1][h];
    if (idx < NN) {
        float v = (s->slot2[idx] >= 0) ? 0.f : elu_f(s->a2[idx * HH + h] * scv + shv);
        s->zd2[(size_t)idx * HH + h] = v;
    } else {
        int q = idx - NN, b = q >> 1, j0 = q & 1;
        int m = s->m2;
        for (int j = j0; j < m; j += 2) {
            int n = s->list2[j];
            float v = (s->a2[n * HH + h] + s->dy2[(size_t)(b * m + j) * HH + h]) * scv + shv;
            s->zd2[(size_t)(NN + b * m + j) * HH + h] = elu_f(v);
        }
    }
}

// ---------------------------------------------------------------------------
// layer-3 fused stats+finalize+output: grid 96 + NN
// ---------------------------------------------------------------------------
__global__ __launch_bounds__(256, 8) void k_outf(Scratch* s, const float* __restrict__ gamma,
                                                 const float* __restrict__ beta,
                                                 float4* __restrict__ out) {
    int bb = blockIdx.x, t = threadIdx.x;
    if (bb < 96) { stats_fin(s, gamma, beta, 3, bb, t); return; }
    wait_flag(&s->flg[2]);
    int n = bb - 96;
    int hq = (t & 63);
    int bq = t >> 6;
    const float4* a4 = (const float4*)(s->a3 + n * HH);
    float4 av = a4[hq];
    float sc0 = s->sc[2][hq*4], sc1 = s->sc[2][hq*4+1], sc2 = s->sc[2][hq*4+2], sc3 = s->sc[2][hq*4+3];
    float sh0 = s->sh[2][hq*4], sh1 = s->sh[2][hq*4+1], sh2 = s->sh[2][hq*4+2], sh3 = s->sh[2][hq*4+3];
    int sl = s->slot3[n];
    int m3 = s->m3;
    for (int b = bq; b < BB; b += 4) {
        float4 v = av;
        if (sl >= 0) {
            float4 dv = *(const float4*)(s->dy3 + (size_t)(b * m3 + sl) * HH + hq*4);
            v.x += dv.x; v.y += dv.y; v.z += dv.z; v.w += dv.w;
        }
        float4 o;
        o.x = elu_f(v.x * sc0 + sh0);
        o.y = elu_f(v.y * sc1 + sh1);
        o.z = elu_f(v.z * sc2 + sh2);
        o.w = elu_f(v.w * sc3 + sh3);
        out[((size_t)b * NN + n) * 64 + hq] = o;
    }
}

// ---------------------------------------------------------------------------
extern "C" void kernel_launch(void* const* d_in, const int* in_sizes, int n_in,
                              void* d_out, int out_size) {
    const float* sensor = (const float*)d_in[0];
    const float* basev  = (const float*)d_in[1];
    const int* ei       = (const int*)d_in[2];
    const float* W1 = (const float*)d_in[3];  const float* b1 = (const float*)d_in[4];
    const float* gm1 = (const float*)d_in[5]; const float* be1 = (const float*)d_in[6];
    const float* W2 = (const float*)d_in[7];  const float* b2 = (const float*)d_in[8];
    const float* gm2 = (const float*)d_in[9]; const float* be2 = (const float*)d_in[10];
    const float* W3 = (const float*)d_in[11]; const float* b3 = (const float*)d_in[12];
    const float* gm3 = (const float*)d_in[13];const float* be3 = (const float*)d_in[14];

    void* sp = nullptr;
    cudaGetSymbolAddress(&sp, S);
    Scratch* s = (Scratch*)sp;

    const int GBIG = (ZROWS + 63) / 64;

    k_initgraph<<<322, 512>>>(s, ei);
    k_gemm1<<<dim3(10, 2, 8), 256>>>(basev, sensor, W1, s->hb);
    k_agg1<<<NN, 256>>>(s, b1);
    k_zd1f<<<16 + NN + BB, 256>>>(s, gm1, be1);

    k_gemm<<<dim3(GBIG, 2), 256>>>(s->zd1, W2, s->g2, NN, &s->m1, BB);
    k_aggs<<<NN + BB * 8, 256>>>(s, b2, 2);
    k_zd2f<<<96 + NN + BB * 2, 256>>>(s, gm2, be2);

    k_gemm<<<dim3(GBIG, 2), 256>>>(s->zd2, W3, s->g3, NN, &s->m2, BB);
    k_aggs<<<NN + BB * 8, 256>>>(s, b3, 3);
    k_outf<<<96 + NN, 256>>>(s, gm3, be3, (float4*)d_out);
}

// round 17
// speedup vs baseline: 1.3606x; 1.3606x over previous
#include <cuda_runtime.h>
#include <math.h>

#define BB   128
#define NKG  500
#define NN   502
#define DD   1024
#define HH   256
#define EE   4000
#define NBTOT (BB*NN)
#define ZROWS (NN + BB*NN)
#define MSUB  (EE + NN)

typedef unsigned long long ull;

struct __align__(16) Scratch {
    float hb[640*HH];
    float a1[NN*HH], a2[NN*HH], a3[NN*HH];
    float zd1[(size_t)ZROWS*HH];
    float g2 [(size_t)ZROWS*HH];
    float zd2[(size_t)ZROWS*HH];
    float g3 [(size_t)ZROWS*HH];
    float dy2[(size_t)BB*NN*HH];
    float dy3[(size_t)BB*NN*HH];
    float csr_norm[EE];
    float sub2_nrm[MSUB], sub3_nrm[MSUB];
    float c[NN], dinv[NN];
    float accA[3][HH], accAsq[3][HH], accD[3][HH], accDsq[3][HH], accAD[3][HH];
    float accS[HH], accS2[HH], accAc[HH];
    float sc[3][HH], sh[3][HH];
    int   csr_src[EE];
    int   sub2_src[MSUB], sub3_src[MSUB];
    int   off[NN+1], soff2[NN+1], soff3[NN+1];
    int   slot1[NN], slot2[NN], slot3[NN];
    int   list1[NN], list2[NN], list3[NN];
    int   m1, m2, m3;
    int   ctr[4];
};
__device__ Scratch S;

__device__ __forceinline__ float elu_f(float x) { return x > 0.f ? x : expm1f(x); }
__device__ __forceinline__ int clampn(int v) { return v < 0 ? 0 : (v >= NN ? NN - 1 : v); }
__device__ __forceinline__ void fma2(ull& d, ull a, ull b) {
    asm("fma.rn.f32x2 %0, %1, %2, %0;" : "+l"(d) : "l"(a), "l"(b));
}
__device__ __forceinline__ ull pk2(float x) {
    ull r; asm("mov.b64 %0, {%1, %1};" : "=l"(r) : "f"(x)); return r;
}

// ---------------------------------------------------------------------------
__global__ void k_init(Scratch* s) {
    int bb = blockIdx.x, t = threadIdx.x;
    if (bb < 640) {
        s->hb[(size_t)bb*HH + t] = 0.f;
    } else {
        for (int l = 0; l < 3; l++) {
            s->accA[l][t]=0.f; s->accAsq[l][t]=0.f;
            s->accD[l][t]=0.f; s->accDsq[l][t]=0.f; s->accAD[l][t]=0.f;
        }
        s->accS[t]=0.f; s->accS2[t]=0.f; s->accAc[t]=0.f;
        if (t < 4) s->ctr[t] = 0;
    }
}

// ---------------------------------------------------------------------------
// graph topology, single block; edge list cached once in shared as u16
// ---------------------------------------------------------------------------
__global__ void k_graph(Scratch* s, const int* __restrict__ ei) {
    __shared__ unsigned short esrc[EE], edst[EE];
    __shared__ int   cnt[NN];
    __shared__ int   sm[512];
    __shared__ float dsh[NN];
    __shared__ float cc[NN];
    __shared__ int   sl1[NN];
    __shared__ int   sl2[NN];
    __shared__ int   mk[NN];
    __shared__ int   lst[NN];
    __shared__ int   mcur;
    int t = threadIdx.x;

    for (int e = t; e < EE; e += 512) {
        esrc[e] = (unsigned short)clampn(ei[e]);
        edst[e] = (unsigned short)clampn(ei[EE + e]);
    }
    if (t < NN) cnt[t] = 0;
    __syncthreads();
    for (int e = t; e < EE; e += 512) atomicAdd(&cnt[edst[e]], 1);
    __syncthreads();

    int deg = (t < NN) ? cnt[t] : 0;
    float di = rsqrtf((float)(deg + 1));
    if (t < NN) { s->dinv[t] = di; dsh[t] = di; }

    sm[t] = deg; __syncthreads();
    for (int d = 1; d < 512; d <<= 1) {
        int x = (t >= d) ? sm[t - d] : 0; __syncthreads();
        sm[t] += x; __syncthreads();
    }
    if (t < NN) s->off[t] = sm[t] - deg;
    if (t == 0) s->off[NN] = sm[NN - 1];
    if (t < NN) cnt[t] = 0;
    __syncthreads();

    for (int e = t; e < EE; e += 512) {
        int src = esrc[e], dst = edst[e];
        int p = s->off[dst] + atomicAdd(&cnt[dst], 1);
        s->csr_src[p] = src;
        s->csr_norm[p] = dsh[src] * dsh[dst];
    }

    if (t < NN) cc[t] = 0.f;
    __syncthreads();
    for (int e = t; e < EE; e += 512) {
        if (esrc[e] == NKG) {
            int dst = edst[e];
            atomicAdd(&cc[dst], dsh[NKG] * dsh[dst]);
        }
    }
    __syncthreads();
    if (t == NKG) cc[t] += dsh[NKG] * dsh[NKG];
    __syncthreads();
    if (t < NN) s->c[t] = cc[t];

    // compact 1
    int f = (t < NN) && (cc[t] > 0.f);
    sm[t] = f; __syncthreads();
    for (int d = 1; d < 512; d <<= 1) {
        int x = (t >= d) ? sm[t - d] : 0; __syncthreads();
        sm[t] += x; __syncthreads();
    }
    if (t < NN) {
        int sl = f ? sm[t] - 1 : -1;
        sl1[t] = sl; s->slot1[t] = sl;
        if (f) s->list1[sm[t] - 1] = t;
    }
    if (t == 0) s->m1 = sm[NN - 1];
    __syncthreads();

    // mark2 + compact 2
    if (t < NN) mk[t] = (sl1[t] >= 0) ? 1 : 0;
    __syncthreads();
    for (int e = t; e < EE; e += 512)
        if (sl1[esrc[e]] >= 0) mk[edst[e]] = 1;
    __syncthreads();
    f = (t < NN) && mk[t];
    sm[t] = f; __syncthreads();
    for (int d = 1; d < 512; d <<= 1) {
        int x = (t >= d) ? sm[t - d] : 0; __syncthreads();
        sm[t] += x; __syncthreads();
    }
    if (t < NN) {
        int sl = f ? sm[t] - 1 : -1;
        sl2[t] = sl; s->slot2[t] = sl;
        if (f) { s->list2[sm[t] - 1] = t; lst[sm[t] - 1] = t; }
    }
    if (t == 0) { s->m2 = sm[NN - 1]; mcur = sm[NN - 1]; }
    __syncthreads();

    // sub-CSR layer 2
    {
        int degj = 0;
        if (t < mcur) {
            int n = lst[t];
            if (sl1[n] >= 0) degj++;
            int e1 = s->off[n + 1];
            for (int e = s->off[n]; e < e1; e++)
                if (sl1[s->csr_src[e]] >= 0) degj++;
        }
        sm[t] = degj; __syncthreads();
        for (int d = 1; d < 512; d <<= 1) {
            int x = (t >= d) ? sm[t - d] : 0; __syncthreads();
            sm[t] += x; __syncthreads();
        }
        if (t < mcur) {
            int o = sm[t] - degj;
            s->soff2[t] = o;
            int n = lst[t];
            if (sl1[n] >= 0) { s->sub2_src[o] = sl1[n]; s->sub2_nrm[o] = dsh[n]*dsh[n]; o++; }
            int e1 = s->off[n + 1];
            for (int e = s->off[n]; e < e1; e++) {
                int sp = sl1[s->csr_src[e]];
                if (sp >= 0) { s->sub2_src[o] = sp; s->sub2_nrm[o] = s->csr_norm[e]; o++; }
            }
        }
        if (t == 0) s->soff2[mcur] = sm[511];
        __syncthreads();
    }

    // mark3 + compact 3
    if (t < NN) mk[t] = (sl2[t] >= 0) ? 1 : 0;
    __syncthreads();
    for (int e = t; e < EE; e += 512)
        if (sl2[esrc[e]] >= 0) mk[edst[e]] = 1;
    __syncthreads();
    f = (t < NN) && mk[t];
    sm[t] = f; __syncthreads();
    for (int d = 1; d < 512; d <<= 1) {
        int x = (t >= d) ? sm[t - d] : 0; __syncthreads();
        sm[t] += x; __syncthreads();
    }
    if (t < NN) {
        s->slot3[t] = f ? sm[t] - 1 : -1;
        if (f) { s->list3[sm[t] - 1] = t; lst[sm[t] - 1] = t; }
    }
    if (t == 0) { s->m3 = sm[NN - 1]; mcur = sm[NN - 1]; }
    __syncthreads();

    // sub-CSR layer 3
    {
        int degj = 0;
        if (t < mcur) {
            int n = lst[t];
            if (sl2[n] >= 0) degj++;
            int e1 = s->off[n + 1];
            for (int e = s->off[n]; e < e1; e++)
                if (sl2[s->csr_src[e]] >= 0) degj++;
        }
        sm[t] = degj; __syncthreads();
        for (int d = 1; d < 512; d <<= 1) {
            int x = (t >= d) ? sm[t - d] : 0; __syncthreads();
            sm[t] += x; __syncthreads();
        }
        if (t < mcur) {
            int o = sm[t] - degj;
            s->soff3[t] = o;
            int n = lst[t];
            if (sl2[n] >= 0) { s->sub3_src[o] = sl2[n]; s->sub3_nrm[o] = dsh[n]*dsh[n]; o++; }
            int e1 = s->off[n + 1];
            for (int e = s->off[n]; e < e1; e++) {
                int sp = sl2[s->csr_src[e]];
                if (sp >= 0) { s->sub3_src[o] = sp; s->sub3_nrm[o] = s->csr_norm[e]; o++; }
            }
        }
        if (t == 0) s->soff3[mcur] = sm[511];
    }
}

// ---------------------------------------------------------------------------
// layer-1 GEMM: 64x128 tile, split-K 8, f32x2, atomic accumulate
// ---------------------------------------------------------------------------
__global__ void k_gemm1(const float* __restrict__ basev, const float* __restrict__ sensor,
                        const float* __restrict__ W, float* __restrict__ hb) {
    int rb = blockIdx.x * 64, cb = blockIdx.y * 128, kc = blockIdx.z * 128;
    __shared__ __align__(16) float As[16][64];
    __shared__ __align__(16) float Ws[16][128];
    int tid = threadIdx.x;
    int tm = (tid >> 4) << 2, tn = (tid & 15) << 3;
    ull acc[4][4];
#pragma unroll
    for (int i = 0; i < 4; i++)
#pragma unroll
        for (int j = 0; j < 4; j++) acc[i][j] = 0ull;
    int r = tid >> 2, kk = (tid & 3) << 2;
    for (int k0 = kc; k0 < kc + 128; k0 += 16) {
        {
            int row = rb + r;
            float4 av = make_float4(0.f, 0.f, 0.f, 0.f);
            if (row < NKG)           av = *(const float4*)(basev  + (size_t)row * DD + k0 + kk);
            else if (row < NKG + BB) av = *(const float4*)(sensor + (size_t)(row - NKG) * DD + k0 + kk);
            As[kk][r]=av.x; As[kk+1][r]=av.y; As[kk+2][r]=av.z; As[kk+3][r]=av.w;
        }
#pragma unroll
        for (int ld = 0; ld < 2; ld++) {
            int idx = tid + ld * 256;
            int wr = idx >> 5, wc = (idx & 31) << 2;
            *(float4*)&Ws[wr][wc] = *(const float4*)(W + (size_t)(k0 + wr) * HH + cb + wc);
        }
        __syncthreads();
#pragma unroll
        for (int q = 0; q < 16; q++) {
            float4 a = *(const float4*)&As[q][tm];
            ull b0 = *(const ull*)&Ws[q][tn];
            ull b1 = *(const ull*)&Ws[q][tn+2];
            ull b2 = *(const ull*)&Ws[q][tn+4];
            ull b3 = *(const ull*)&Ws[q][tn+6];
            ull ap0 = pk2(a.x), ap1 = pk2(a.y), ap2 = pk2(a.z), ap3 = pk2(a.w);
            fma2(acc[0][0],ap0,b0); fma2(acc[0][1],ap0,b1); fma2(acc[0][2],ap0,b2); fma2(acc[0][3],ap0,b3);
            fma2(acc[1][0],ap1,b0); fma2(acc[1][1],ap1,b1); fma2(acc[1][2],ap1,b2); fma2(acc[1][3],ap1,b3);
            fma2(acc[2][0],ap2,b0); fma2(acc[2][1],ap2,b1); fma2(acc[2][2],ap2,b2); fma2(acc[2][3],ap2,b3);
            fma2(acc[3][0],ap3,b0); fma2(acc[3][1],ap3,b1); fma2(acc[3][2],ap3,b2); fma2(acc[3][3],ap3,b3);
        }
        __syncthreads();
    }
#pragma unroll
    for (int i = 0; i < 4; i++) {
        int row = rb + tm + i;
        if (row < NKG + BB) {
            float* p = hb + (size_t)row * HH + cb + tn;
#pragma unroll
            for (int j = 0; j < 4; j++) {
                float2 v = *reinterpret_cast<float2*>(&acc[i][j]);
                atomicAdd(p + 2*j, v.x); atomicAdd(p + 2*j + 1, v.y);
            }
        }
    }
}

// ---------------------------------------------------------------------------
// generic GEMM: C[M,256] = A[M,256] @ W[256,256], 64x128, f32x2
// ---------------------------------------------------------------------------
__global__ void k_gemm(const float* __restrict__ A, const float* __restrict__ W,
                       float* __restrict__ C, int Mbase,
                       const int* __restrict__ mptr, int mmul) {
    int M = Mbase + (mptr ? (*mptr) * mmul : 0);
    int rb = blockIdx.x * 64;
    if (rb >= M) return;
    int cb = blockIdx.y * 128;
    __shared__ __align__(16) float As[16][64];
    __shared__ __align__(16) float Ws[16][128];
    int tid = threadIdx.x;
    int tm = (tid >> 4) << 2, tn = (tid & 15) << 3;
    ull acc[4][4];
#pragma unroll
    for (int i = 0; i < 4; i++)
#pragma unroll
        for (int j = 0; j < 4; j++) acc[i][j] = 0ull;
    int r = tid >> 2, kk = (tid & 3) << 2;
    for (int k0 = 0; k0 < HH; k0 += 16) {
        {
            float4 av = make_float4(0.f, 0.f, 0.f, 0.f);
            if (rb + r < M) av = *(const float4*)(A + (size_t)(rb + r) * HH + k0 + kk);
            As[kk][r]=av.x; As[kk+1][r]=av.y; As[kk+2][r]=av.z; As[kk+3][r]=av.w;
        }
#pragma unroll
        for (int ld = 0; ld < 2; ld++) {
            int idx = tid + ld * 256;
            int wr = idx >> 5, wc = (idx & 31) << 2;
            *(float4*)&Ws[wr][wc] = *(const float4*)(W + (size_t)(k0 + wr) * HH + cb + wc);
        }
        __syncthreads();
#pragma unroll
        for (int q = 0; q < 16; q++) {
            float4 a = *(const float4*)&As[q][tm];
            ull b0 = *(const ull*)&Ws[q][tn];
            ull b1 = *(const ull*)&Ws[q][tn+2];
            ull b2 = *(const ull*)&Ws[q][tn+4];
            ull b3 = *(const ull*)&Ws[q][tn+6];
            ull ap0 = pk2(a.x), ap1 = pk2(a.y), ap2 = pk2(a.z), ap3 = pk2(a.w);
            fma2(acc[0][0],ap0,b0); fma2(acc[0][1],ap0,b1); fma2(acc[0][2],ap0,b2); fma2(acc[0][3],ap0,b3);
            fma2(acc[1][0],ap1,b0); fma2(acc[1][1],ap1,b1); fma2(acc[1][2],ap1,b2); fma2(acc[1][3],ap1,b3);
            fma2(acc[2][0],ap2,b0); fma2(acc[2][1],ap2,b1); fma2(acc[2][2],ap2,b2); fma2(acc[2][3],ap2,b3);
            fma2(acc[3][0],ap3,b0); fma2(acc[3][1],ap3,b1); fma2(acc[3][2],ap3,b2); fma2(acc[3][3],ap3,b3);
        }
        __syncthreads();
    }
#pragma unroll
    for (int i = 0; i < 4; i++) {
        int row = rb + tm + i;
        if (row < M) {
            ull* p = (ull*)(C + (size_t)row * HH + cb + tn);
            p[0]=acc[i][0]; p[1]=acc[i][1]; p[2]=acc[i][2]; p[3]=acc[i][3];
        }
    }
}

// ---------------------------------------------------------------------------
// layer-1: PURE base aggregation — grid NN  (measured 6 µs vs 18 µs fused)
// ---------------------------------------------------------------------------
__global__ void k_agg1(Scratch* s, const float* __restrict__ b1) {
    int n = blockIdx.x, h = threadIdx.x;
    float acc = b1[h];
    int e0 = s->off[n], e1 = s->off[n + 1];
    int e = e0;
    for (; e + 3 < e1; e += 4) {
        int s0 = s->csr_src[e],   s1x = s->csr_src[e+1];
        int s2 = s->csr_src[e+2], s3x = s->csr_src[e+3];
        float n0 = s->csr_norm[e],   n1 = s->csr_norm[e+1];
        float n2 = s->csr_norm[e+2], n3 = s->csr_norm[e+3];
        float v0 = (s0  < NKG) ? s->hb[(size_t)s0  * HH + h] : 0.f;
        float v1 = (s1x < NKG) ? s->hb[(size_t)s1x * HH + h] : 0.f;
        float v2 = (s2  < NKG) ? s->hb[(size_t)s2  * HH + h] : 0.f;
        float v3 = (s3x < NKG) ? s->hb[(size_t)s3x * HH + h] : 0.f;
        acc += n0*v0 + n1*v1 + n2*v2 + n3*v3;
    }
    for (; e < e1; e++) {
        int src = s->csr_src[e];
        if (src < NKG) acc += s->csr_norm[e] * s->hb[(size_t)src * HH + h];
    }
    float di = s->dinv[n];
    if (n < NKG) acc += di * di * s->hb[(size_t)n * HH + h];
    s->a1[n * HH + h] = acc;
}

// ---------------------------------------------------------------------------
// layer-1 BN stats + finalize, 16 blocks (low atomic fan-in)
// ---------------------------------------------------------------------------
__global__ void k_sf1(Scratch* s, const float* __restrict__ gamma,
                      const float* __restrict__ beta) {
    int bb = blockIdx.x, h = threadIdx.x;
    if (bb < 12) {
        float sA = 0.f, sA2 = 0.f, sAc = 0.f;
        for (int n = bb; n < NN; n += 12) {
            float A = s->a1[n * HH + h], cv = s->c[n];
            sA += A; sA2 += A * A; sAc += A * cv;
        }
        atomicAdd(&s->accA[0][h], sA);
        atomicAdd(&s->accAsq[0][h], sA2);
        atomicAdd(&s->accAc[h], sAc);
    } else {
        int k = bb - 12;
        float ss = 0.f, ss2 = 0.f;
        for (int b = k; b < BB; b += 4) {
            float v = s->hb[(size_t)(NKG + b) * HH + h];
            ss += v; ss2 += v * v;
        }
        atomicAdd(&s->accS[h], ss);
        atomicAdd(&s->accS2[h], ss2);
    }
    __threadfence();
    __syncthreads();
    __shared__ int ticket;
    if (h == 0) ticket = atomicAdd(&s->ctr[0], 1);
    __syncthreads();
    if (ticket == (int)gridDim.x - 1) {
        __threadfence();
        __shared__ float r1[256], r2[256];
        float lc = 0.f, lc2 = 0.f;
        for (int n = h; n < NN; n += 256) { float cv = s->c[n]; lc += cv; lc2 += cv * cv; }
        r1[h] = lc; r2[h] = lc2; __syncthreads();
        for (int d = 128; d > 0; d >>= 1) {
            if (h < d) { r1[h] += r1[h + d]; r2[h] += r2[h + d]; }
            __syncthreads();
        }
        float Ec  = r1[0] / NN, Ec2 = r2[0] / NN;
        float EA  = s->accA[0][h] / NN, EA2 = s->accAsq[0][h] / NN, EAc = s->accAc[h] / NN;
        float Es  = s->accS[h] / BB,  Es2 = s->accS2[h] / BB;
        float mu  = EA + Ec * Es;
        float ey2 = EA2 + 2.f * EAc * Es + Ec2 * Es2;
        float rstd = rsqrtf(ey2 - mu * mu + 1e-5f);
        float scv = rstd * gamma[h];
        s->sc[0][h] = scv; s->sh[0][h] = beta[h] - mu * scv;
    }
}

// ---------------------------------------------------------------------------
// BN+ELU materialization into fused [zb; d]   (exact R6 body)
// ---------------------------------------------------------------------------
__global__ void k_zd(Scratch* s, int layer) {
    int bb = blockIdx.x, h = threadIdx.x;
    if (layer == 1) {
        float scv = s->sc[0][h], shv = s->sh[0][h];
        if (bb < NN) {
            float v = (s->slot1[bb] >= 0) ? 0.f : elu_f(s->a1[bb * HH + h] * scv + shv);
            s->zd1[(size_t)bb * HH + h] = v;
        } else {
            int b = bb - NN, m = s->m1;
            float sv = s->hb[(size_t)(NKG + b) * HH + h];
            for (int j = 0; j < m; j++) {
                int n = s->list1[j];
                float v = (s->a1[n * HH + h] + s->c[n] * sv) * scv + shv;
                s->zd1[(size_t)(NN + b * m + j) * HH + h] = elu_f(v);
            }
        }
    } else {
        float scv = s->sc[1][h], shv = s->sh[1][h];
        if (bb < NN) {
            float v = (s->slot2[bb] >= 0) ? 0.f : elu_f(s->a2[bb * HH + h] * scv + shv);
            s->zd2[(size_t)bb * HH + h] = v;
        } else {
            int idx = bb - NN, b = idx >> 2, j0 = idx & 3;
            int m = s->m2;
            for (int j = j0; j < m; j += 4) {
                int n = s->list2[j];
                float v = (s->a2[n * HH + h] + s->dy2[(size_t)(b * m + j) * HH + h]) * scv + shv;
                s->zd2[(size_t)(NN + b * m + j) * HH + h] = elu_f(v);
            }
        }
    }
}

// ---------------------------------------------------------------------------
// layers 2/3: combined base agg (+statsA) and dep agg (exact R6 body)
// grid = NN + BB*8
// ---------------------------------------------------------------------------
__global__ void k_aggs(Scratch* s, const float* __restrict__ bias, int layer) {
    int bb = blockIdx.x, h = threadIdx.x, L = layer - 1;
    const float* g = (layer == 2) ? s->g2 : s->g3;
    if (bb < NN) {
        int n = bb;
        float di = s->dinv[n];
        float acc = bias[h] + di * di * g[(size_t)n * HH + h];
        int e1 = s->off[n + 1];
        for (int e = s->off[n]; e < e1; e++)
            acc += s->csr_norm[e] * g[(size_t)s->csr_src[e] * HH + h];
        ((layer == 2) ? s->a2 : s->a3)[n * HH + h] = acc;
        atomicAdd(&s->accA[L][h], acc);
        atomicAdd(&s->accAsq[L][h], acc * acc);
    } else {
        int idx = bb - NN, b = idx >> 3, j0 = idx & 7;
        int m  = (layer == 2) ? s->m2 : s->m3;
        int mp = (layer == 2) ? s->m1 : s->m2;
        const int*   soff = (layer == 2) ? s->soff2 : s->soff3;
        const int*   ssrc = (layer == 2) ? s->sub2_src : s->sub3_src;
        const float* snrm = (layer == 2) ? s->sub2_nrm : s->sub3_nrm;
        float* dy = (layer == 2) ? s->dy2 : s->dy3;
        const float* gb = g + (size_t)(NN + b * mp) * HH + h;
        for (int j = j0; j < m; j += 8) {
            int e0 = soff[j], e1 = soff[j + 1];
            float acc = 0.f;
            int e = e0;
            for (; e + 3 < e1; e += 4) {
                int p0 = ssrc[e],   p1 = ssrc[e+1];
                int p2 = ssrc[e+2], p3 = ssrc[e+3];
                float q0 = snrm[e],   q1 = snrm[e+1];
                float q2 = snrm[e+2], q3 = snrm[e+3];
                acc += q0 * gb[(size_t)p0 * HH] + q1 * gb[(size_t)p1 * HH]
                     + q2 * gb[(size_t)p2 * HH] + q3 * gb[(size_t)p3 * HH];
            }
            for (; e < e1; e++)
                acc += snrm[e] * gb[(size_t)ssrc[e] * HH];
            dy[(size_t)(b * m + j) * HH + h] = acc;
        }
    }
}

// ---------------------------------------------------------------------------
// layers 2/3 stats-D + finalize (ticketed). j-outer loop: no modulo,
// a[list[j]] hoisted out of the b loop.
// ---------------------------------------------------------------------------
__global__ void k_fin23(Scratch* s, const float* __restrict__ gamma,
                        const float* __restrict__ beta, int layer) {
    int h = threadIdx.x, bb = blockIdx.x, L = layer - 1;
    int m = (layer == 2) ? s->m2 : s->m3;
    const float* a = (layer == 2) ? s->a2 : s->a3;
    const float* dy = (layer == 2) ? s->dy2 : s->dy3;
    const int* list = (layer == 2) ? s->list2 : s->list3;
    float sd = 0.f, sd2 = 0.f, sad = 0.f;
    for (int j = bb; j < m; j += gridDim.x) {
        float A = a[list[j] * HH + h];
        const float* dyj = dy + (size_t)j * HH + h;
        float ld = 0.f, ld2 = 0.f, lad = 0.f;
        for (int b = 0; b < BB; b++) {
            float dv = dyj[(size_t)b * m * HH];
            ld += dv; ld2 += dv * dv; lad += dv;
        }
        sd += ld; sd2 += ld2; sad += A * lad;
    }
    atomicAdd(&s->accD[L][h], sd);
    atomicAdd(&s->accDsq[L][h], sd2);
    atomicAdd(&s->accAD[L][h], sad);
    __threadfence();
    __syncthreads();
    __shared__ int ticket;
    if (h == 0) ticket = atomicAdd(&s->ctr[L], 1);
    __syncthreads();
    if (ticket == (int)gridDim.x - 1) {
        __threadfence();
        float mu  = (BB * s->accA[L][h] + s->accD[L][h]) * (1.f / NBTOT);
        float ey2 = (BB * s->accAsq[L][h] + 2.f * s->accAD[L][h] + s->accDsq[L][h]) * (1.f / NBTOT);
        float rstd = rsqrtf(ey2 - mu * mu + 1e-5f);
        float scv = rstd * gamma[h];
        s->sc[L][h] = scv; s->sh[L][h] = beta[h] - mu * scv;
    }
}

// ---------------------------------------------------------------------------
// final output, float4 vectorized (exact R6 body)
// ---------------------------------------------------------------------------
__global__ void k_out(Scratch* s, float4* __restrict__ out) {
    int n = blockIdx.x, t = threadIdx.x;
    int hq = (t & 63);
    int bq = t >> 6;
    const float4* a4 = (const float4*)(s->a3 + n * HH);
    float4 av = a4[hq];
    float sc0 = s->sc[2][hq*4], sc1 = s->sc[2][hq*4+1], sc2 = s->sc[2][hq*4+2], sc3 = s->sc[2][hq*4+3];
    float sh0 = s->sh[2][hq*4], sh1 = s->sh[2][hq*4+1], sh2 = s->sh[2][hq*4+2], sh3 = s->sh[2][hq*4+3];
    int sl = s->slot3[n];
    int m3 = s->m3;
    for (int b = bq; b < BB; b += 4) {
        float4 v = av;
        if (sl >= 0) {
            float4 dv = *(const float4*)(s->dy3 + (size_t)(b * m3 + sl) * HH + hq*4);
            v.x += dv.x; v.y += dv.y; v.z += dv.z; v.w += dv.w;
        }
        float4 o;
        o.x = elu_f(v.x * sc0 + sh0);
        o.y = elu_f(v.y * sc1 + sh1);
        o.z = elu_f(v.z * sc2 + sh2);
        o.w = elu_f(v.w * sc3 + sh3);
        out[((size_t)b * NN + n) * 64 + hq] = o;
    }
}

// ---------------------------------------------------------------------------
extern "C" void kernel_launch(void* const* d_in, const int* in_sizes, int n_in,
                              void* d_out, int out_size) {
    const float* sensor = (const float*)d_in[0];
    const float* basev  = (const float*)d_in[1];
    const int* ei       = (const int*)d_in[2];
    const float* W1 = (const float*)d_in[3];  const float* b1 = (const float*)d_in[4];
    const float* gm1 = (const float*)d_in[5]; const float* be1 = (const float*)d_in[6];
    const float* W2 = (const float*)d_in[7];  const float* b2 = (const float*)d_in[8];
    const float* gm2 = (const float*)d_in[9]; const float* be2 = (const float*)d_in[10];
    const float* W3 = (const float*)d_in[11]; const float* b3 = (const float*)d_in[12];
    const float* gm3 = (const float*)d_in[13];const float* be3 = (const float*)d_in[14];

    void* sp = nullptr;
    cudaGetSymbolAddress(&sp, S);
    Scratch* s = (Scratch*)sp;

    const int GBIG = (ZROWS + 63) / 64;

    k_init<<<641, 256>>>(s);
    k_graph<<<1, 512>>>(s, ei);
    k_gemm1<<<dim3(10, 2, 8), 256>>>(basev, sensor, W1, s->hb);
    k_agg1<<<NN, 256>>>(s, b1);
    k_sf1<<<16, 256>>>(s, gm1, be1);
    k_zd<<<NN + BB, 256>>>(s, 1);

    k_gemm<<<dim3(GBIG, 2), 256>>>(s->zd1, W2, s->g2, NN, &s->m1, BB);
    k_aggs<<<NN + BB * 8, 256>>>(s, b2, 2);
    k_fin23<<<136, 256>>>(s, gm2, be2, 2);
    k_zd<<<NN + BB * 4, 256>>>(s, 2);

    k_gemm<<<dim3(GBIG, 2), 256>>>(s->zd2, W3, s->g3, NN, &s->m2, BB);
    k_aggs<<<NN + BB * 8, 256>>>(s, b3, 3);
    k_fin23<<<264, 256>>>(s, gm3, be3, 3);

    k_out<<<NN, 256>>>(s, (float4*)d_out);
}